// round 14
// baseline (speedup 1.0000x reference)
#include <cuda_runtime.h>
#include <math.h>

// Problem dims (fixed by setup_inputs)
#define BATCH 256
#define DM    512
#define NN    1024
#define KTOT  (2*NN)

// Phase-1 tiling (R11 measured-best config)
#define BT 32
#define NT 32
#define DC 64
#define ZSPLIT 8
#define DPER (DM / ZSPLIT)       // 64 == DC
#define P1_THREADS 256

// Phase-2 tiling (split-K SGEMM, scalar FFMA)
#define BM 64
#define BN 64
#define BK 16
#define SPLITK 16
#define KCHUNK (KTOT / SPLITK)   // 128 (never crosses cos/sin boundary)

// Scratch (static device globals — no allocation allowed).
// Both are RED.ADD accumulators, zeroed by memset nodes each launch.
__device__ float g_sums[BATCH * KTOT];   // resonance sums (2 MB)
__device__ float g_acc[BATCH * DM];      // pre-silu GEMM accumulator (512 KB)

// ---------------------------------------------------------------------------
// FMA-pipe sincos, pi-based reduction, single-step CW (n<=4 here):
// R11-validated (rel_err 7.6e-7 end-to-end).
// ---------------------------------------------------------------------------
__device__ __forceinline__ void sincos_poly(float th, float* so, float* co)
{
    const float MAGIC = 12582912.0f;                   // 1.5 * 2^23
    float kf = fmaf(th, 0.3183098861837907f, MAGIC);   // th/pi + magic
    const int q = __float_as_int(kf);                  // low bits = n
    kf -= MAGIC;                                       // n as float
    const float r = fmaf(kf, -3.14159265358979f, th);  // th - n*pi
    const float u = r * r;
    float sp = fmaf(2.7557319e-6f, u, -1.9841270e-4f);
    sp = fmaf(sp, u, 8.3333333e-3f);
    sp = fmaf(sp, u, -1.6666667e-1f);
    sp = fmaf(sp * u, r, r);                           // sin(r)
    float cp = fmaf(2.4801587e-5f, u, -1.3888889e-3f);
    cp = fmaf(cp, u, 4.1666667e-2f);
    cp = fmaf(cp, u, -0.5f);
    cp = fmaf(cp, u, 1.0f);                            // cos(r)
    const int g = q << 31;                             // (-1)^n sign bit
    *so = __int_as_float(__float_as_int(sp) ^ g);
    *co = __int_as_float(__float_as_int(cp) ^ g);
}

// ---------------------------------------------------------------------------
// Phase 1: 3 MUFU sincos + 1 FMA-pipe poly per d (measured-optimal mix).
// Grid: (32, 8, 8) = 2048 blocks x 256 threads.
// Epilogue: RED.ADD partials straight into g_sums (no slab buffer).
// ---------------------------------------------------------------------------
__global__ void __launch_bounds__(P1_THREADS) phase1_kernel(
    const float* __restrict__ xr, const float* __restrict__ xi,
    const float* __restrict__ W,  const float* __restrict__ Bm)
{
    __shared__ float xsT[DC][BT + 2];
    __shared__ float wbT[DC][2 * NT + 4];

    const int t  = threadIdx.x;
    const int tn = t & 15;
    const int tb = t >> 4;
    const int b0 = blockIdx.y * BT;
    const int n0 = blockIdx.x * NT;
    const int z  = blockIdx.z;
    const int d0 = z * DPER;

    #pragma unroll
    for (int i = t; i < BT * DC; i += P1_THREADS) {
        const int r = i >> 6;
        const int c = i & (DC - 1);
        const int gx = (b0 + r) * DM + d0 + c;
        xsT[c][r] = xr[gx] + xi[gx];
        const int gw = (n0 + r) * DM + d0 + c;
        const float winv = __fdividef(1.0f, 1.0f + fabsf(W[gw]));
        *(float2*)&wbT[c][2 * r] = make_float2(winv, Bm[gw]);
    }
    __syncthreads();

    float aS00 = 0.f, aS01 = 0.f, aS10 = 0.f, aS11 = 0.f;
    float aC00 = 0.f, aC01 = 0.f, aC10 = 0.f, aC11 = 0.f;

    #pragma unroll 8
    for (int d = 0; d < DC; d++) {
        const float2 xv = *(const float2*)&xsT[d][2 * tb];
        const float4 wb = *(const float4*)&wbT[d][4 * tn];
        float s, c;
        __sincosf(fmaf(xv.x, wb.x, wb.y), &s, &c); aS00 += s; aC00 += c;
        __sincosf(fmaf(xv.x, wb.z, wb.w), &s, &c); aS01 += s; aC01 += c;
        __sincosf(fmaf(xv.y, wb.x, wb.y), &s, &c); aS10 += s; aC10 += c;
        sincos_poly(fmaf(xv.y, wb.z, wb.w), &s, &c); aS11 += s; aC11 += c;
    }

    const int br0 = b0 + 2 * tb, br1 = br0 + 1;
    const int nc0 = n0 + 2 * tn, nc1 = nc0 + 1;
    atomicAdd(&g_sums[br0 * KTOT + nc0],      aC00);
    atomicAdd(&g_sums[br0 * KTOT + nc1],      aC01);
    atomicAdd(&g_sums[br1 * KTOT + nc0],      aC10);
    atomicAdd(&g_sums[br1 * KTOT + nc1],      aC11);
    atomicAdd(&g_sums[br0 * KTOT + NN + nc0], aS00);
    atomicAdd(&g_sums[br0 * KTOT + NN + nc1], aS01);
    atomicAdd(&g_sums[br1 * KTOT + NN + nc0], aS10);
    atomicAdd(&g_sums[br1 * KTOT + NN + nc1], aS11);
}

// ---------------------------------------------------------------------------
// Phase 2: split-K SGEMM, scalar FFMA, 4x4 per thread.
// Grid: (DM/64=8, BATCH/64=4, SPLITK=16) = 512 blocks x 256 threads.
// Epilogue: RED.ADD into g_acc (no partial buffer, no reduce pass).
// ---------------------------------------------------------------------------
__global__ void __launch_bounds__(256) phase2_kernel(
    const float* __restrict__ PC, const float* __restrict__ PS)
{
    __shared__ float As[BK][BM + 4];
    __shared__ float Bs[BK][BN + 4];

    const int t  = threadIdx.x;
    const int tx = t & 15;
    const int ty = t >> 4;
    const int m0 = blockIdx.x * BN;
    const int b0 = blockIdx.y * BM;
    const int z  = blockIdx.z;
    const int kbase = z * KCHUNK;

    const float* __restrict__ Wsel = (kbase < NN) ? PC : PS;
    const int koff = (kbase < NN) ? 0 : NN;

    float acc[4][4];
    #pragma unroll
    for (int i = 0; i < 4; i++)
        #pragma unroll
        for (int j = 0; j < 4; j++) acc[i][j] = 0.0f;

    for (int k0 = kbase; k0 < kbase + KCHUNK; k0 += BK) {
        #pragma unroll
        for (int i = t; i < BM * BK; i += 256) {
            const int r  = i >> 4;
            const int kk = i & 15;
            As[kk][r] = g_sums[(b0 + r) * KTOT + k0 + kk];
        }
        #pragma unroll
        for (int i = t; i < BN * BK; i += 256) {
            const int r  = i >> 4;
            const int kk = i & 15;
            Bs[kk][r] = Wsel[(m0 + r) * NN + (k0 + kk - koff)];
        }
        __syncthreads();

        #pragma unroll
        for (int kk = 0; kk < BK; kk++) {
            const float4 av = *(const float4*)&As[kk][ty * 4];
            const float4 bv = *(const float4*)&Bs[kk][tx * 4];
            const float a[4] = {av.x, av.y, av.z, av.w};
            const float b[4] = {bv.x, bv.y, bv.z, bv.w};
            #pragma unroll
            for (int i = 0; i < 4; i++)
                #pragma unroll
                for (int j = 0; j < 4; j++)
                    acc[i][j] = fmaf(a[i], b[j], acc[i][j]);
        }
        __syncthreads();
    }

    #pragma unroll
    for (int i = 0; i < 4; i++) {
        float* row = &g_acc[(b0 + ty * 4 + i) * DM + m0 + tx * 4];
        #pragma unroll
        for (int j = 0; j < 4; j++)
            atomicAdd(&row[j], acc[i][j]);
    }
}

// ---------------------------------------------------------------------------
// SiLU epilogue: out = g_acc * sigmoid(g_acc). One float4 per thread.
// Grid: 128 blocks x 256 threads.
// ---------------------------------------------------------------------------
__global__ void __launch_bounds__(256) silu_kernel(float* __restrict__ out)
{
    const int i = (blockIdx.x * 256 + threadIdx.x) * 4;
    if (i >= BATCH * DM) return;
    const float4 v = *(const float4*)&g_acc[i];
    float4 o;
    o.x = v.x / (1.0f + __expf(-v.x));
    o.y = v.y / (1.0f + __expf(-v.y));
    o.z = v.z / (1.0f + __expf(-v.z));
    o.w = v.w / (1.0f + __expf(-v.w));
    *(float4*)&out[i] = o;
}

extern "C" void kernel_launch(void* const* d_in, const int* in_sizes, int n_in,
                              void* d_out, int out_size)
{
    (void)in_sizes; (void)n_in; (void)out_size;
    const float* xr = (const float*)d_in[0];
    const float* xi = (const float*)d_in[1];
    const float* W  = (const float*)d_in[2];
    const float* Bm = (const float*)d_in[3];
    const float* PC = (const float*)d_in[4];
    const float* PS = (const float*)d_in[5];
    float* out = (float*)d_out;

    // Zero the RED accumulators (graph-legal memset nodes; no allocation).
    void* p_sums = nullptr;
    void* p_acc  = nullptr;
    cudaGetSymbolAddress(&p_sums, g_sums);
    cudaGetSymbolAddress(&p_acc,  g_acc);
    cudaMemsetAsync(p_sums, 0, (size_t)BATCH * KTOT * sizeof(float));
    cudaMemsetAsync(p_acc,  0, (size_t)BATCH * DM   * sizeof(float));

    dim3 g1(NN / NT, BATCH / BT, ZSPLIT);      // 2048 blocks
    phase1_kernel<<<g1, P1_THREADS>>>(xr, xi, W, Bm);

    dim3 g2(DM / BN, BATCH / BM, SPLITK);      // 8 x 4 x 16 = 512 blocks
    phase2_kernel<<<g2, 256>>>(PC, PS);

    silu_kernel<<<BATCH * DM / 4 / 256, 256>>>(out);   // 128 blocks
}

// round 15
// speedup vs baseline: 1.0353x; 1.0353x over previous
#include <cuda_runtime.h>
#include <math.h>

// Problem dims (fixed by setup_inputs)
#define BATCH 256
#define DM    512
#define NN    1024
#define KTOT  (2*NN)

// Phase-1 tiling (R11/R14 measured-best config)
#define BT 32
#define NT 32
#define DC 64
#define ZSPLIT 8
#define DPER (DM / ZSPLIT)       // 64 == DC
#define P1_THREADS 256

// Phase-2 tiling (split-K SGEMM, scalar FFMA)
#define BM 64
#define BN 64
#define BK 16
#define SPLITK 16
#define KCHUNK (KTOT / SPLITK)   // 128 (never crosses cos/sin boundary)

// Scratch (static device globals — no allocation allowed).
__device__ float g_sums[BATCH * KTOT];        // RED.ADD accumulator (2 MB, memset)
__device__ float g_part[SPLITK * BATCH * DM]; // split-K partials (8 MB)

// ---------------------------------------------------------------------------
// FMA-pipe sincos, pi-based reduction, single-step CW (n<=4 here):
// R11/R14-validated (rel_err ~7.6e-7 end-to-end).
// ---------------------------------------------------------------------------
__device__ __forceinline__ void sincos_poly(float th, float* so, float* co)
{
    const float MAGIC = 12582912.0f;                   // 1.5 * 2^23
    float kf = fmaf(th, 0.3183098861837907f, MAGIC);   // th/pi + magic
    const int q = __float_as_int(kf);                  // low bits = n
    kf -= MAGIC;                                       // n as float
    const float r = fmaf(kf, -3.14159265358979f, th);  // th - n*pi
    const float u = r * r;
    float sp = fmaf(2.7557319e-6f, u, -1.9841270e-4f);
    sp = fmaf(sp, u, 8.3333333e-3f);
    sp = fmaf(sp, u, -1.6666667e-1f);
    sp = fmaf(sp * u, r, r);                           // sin(r)
    float cp = fmaf(2.4801587e-5f, u, -1.3888889e-3f);
    cp = fmaf(cp, u, 4.1666667e-2f);
    cp = fmaf(cp, u, -0.5f);
    cp = fmaf(cp, u, 1.0f);                            // cos(r)
    const int g = q << 31;                             // (-1)^n sign bit
    *so = __int_as_float(__float_as_int(sp) ^ g);
    *co = __int_as_float(__float_as_int(cp) ^ g);
}

// ---------------------------------------------------------------------------
// Phase 1: 3 MUFU sincos + 1 FMA-pipe poly per d (measured-optimal mix).
// Grid: (32, 8, 8) = 2048 blocks x 256 threads.
// Epilogue: RED.ADD straight into g_sums (measured free vs stores; kills the
// combine kernel and 16 MB of slab traffic).
// ---------------------------------------------------------------------------
__global__ void __launch_bounds__(P1_THREADS) phase1_kernel(
    const float* __restrict__ xr, const float* __restrict__ xi,
    const float* __restrict__ W,  const float* __restrict__ Bm)
{
    __shared__ float xsT[DC][BT + 2];
    __shared__ float wbT[DC][2 * NT + 4];

    const int t  = threadIdx.x;
    const int tn = t & 15;
    const int tb = t >> 4;
    const int b0 = blockIdx.y * BT;
    const int n0 = blockIdx.x * NT;
    const int z  = blockIdx.z;
    const int d0 = z * DPER;

    #pragma unroll
    for (int i = t; i < BT * DC; i += P1_THREADS) {
        const int r = i >> 6;
        const int c = i & (DC - 1);
        const int gx = (b0 + r) * DM + d0 + c;
        xsT[c][r] = xr[gx] + xi[gx];
        const int gw = (n0 + r) * DM + d0 + c;
        const float winv = __fdividef(1.0f, 1.0f + fabsf(W[gw]));
        *(float2*)&wbT[c][2 * r] = make_float2(winv, Bm[gw]);
    }
    __syncthreads();

    float aS00 = 0.f, aS01 = 0.f, aS10 = 0.f, aS11 = 0.f;
    float aC00 = 0.f, aC01 = 0.f, aC10 = 0.f, aC11 = 0.f;

    #pragma unroll 8
    for (int d = 0; d < DC; d++) {
        const float2 xv = *(const float2*)&xsT[d][2 * tb];
        const float4 wb = *(const float4*)&wbT[d][4 * tn];
        float s, c;
        __sincosf(fmaf(xv.x, wb.x, wb.y), &s, &c); aS00 += s; aC00 += c;
        __sincosf(fmaf(xv.x, wb.z, wb.w), &s, &c); aS01 += s; aC01 += c;
        __sincosf(fmaf(xv.y, wb.x, wb.y), &s, &c); aS10 += s; aC10 += c;
        sincos_poly(fmaf(xv.y, wb.z, wb.w), &s, &c); aS11 += s; aC11 += c;
    }

    const int br0 = b0 + 2 * tb, br1 = br0 + 1;
    const int nc0 = n0 + 2 * tn, nc1 = nc0 + 1;
    atomicAdd(&g_sums[br0 * KTOT + nc0],      aC00);
    atomicAdd(&g_sums[br0 * KTOT + nc1],      aC01);
    atomicAdd(&g_sums[br1 * KTOT + nc0],      aC10);
    atomicAdd(&g_sums[br1 * KTOT + nc1],      aC11);
    atomicAdd(&g_sums[br0 * KTOT + NN + nc0], aS00);
    atomicAdd(&g_sums[br0 * KTOT + NN + nc1], aS01);
    atomicAdd(&g_sums[br1 * KTOT + NN + nc0], aS10);
    atomicAdd(&g_sums[br1 * KTOT + NN + nc1], aS11);
}

// ---------------------------------------------------------------------------
// Phase 2: split-K SGEMM, scalar FFMA, 4x4 per thread, STG.128 partials.
// Grid: (DM/64=8, BATCH/64=4, SPLITK=16) = 512 blocks x 256 threads.
// ---------------------------------------------------------------------------
__global__ void __launch_bounds__(256) phase2_kernel(
    const float* __restrict__ PC, const float* __restrict__ PS)
{
    __shared__ float As[BK][BM + 4];
    __shared__ float Bs[BK][BN + 4];

    const int t  = threadIdx.x;
    const int tx = t & 15;
    const int ty = t >> 4;
    const int m0 = blockIdx.x * BN;
    const int b0 = blockIdx.y * BM;
    const int z  = blockIdx.z;
    const int kbase = z * KCHUNK;

    const float* __restrict__ Wsel = (kbase < NN) ? PC : PS;
    const int koff = (kbase < NN) ? 0 : NN;

    float acc[4][4];
    #pragma unroll
    for (int i = 0; i < 4; i++)
        #pragma unroll
        for (int j = 0; j < 4; j++) acc[i][j] = 0.0f;

    for (int k0 = kbase; k0 < kbase + KCHUNK; k0 += BK) {
        #pragma unroll
        for (int i = t; i < BM * BK; i += 256) {
            const int r  = i >> 4;
            const int kk = i & 15;
            As[kk][r] = g_sums[(b0 + r) * KTOT + k0 + kk];
        }
        #pragma unroll
        for (int i = t; i < BN * BK; i += 256) {
            const int r  = i >> 4;
            const int kk = i & 15;
            Bs[kk][r] = Wsel[(m0 + r) * NN + (k0 + kk - koff)];
        }
        __syncthreads();

        #pragma unroll
        for (int kk = 0; kk < BK; kk++) {
            const float4 av = *(const float4*)&As[kk][ty * 4];
            const float4 bv = *(const float4*)&Bs[kk][tx * 4];
            const float a[4] = {av.x, av.y, av.z, av.w};
            const float b[4] = {bv.x, bv.y, bv.z, bv.w};
            #pragma unroll
            for (int i = 0; i < 4; i++)
                #pragma unroll
                for (int j = 0; j < 4; j++)
                    acc[i][j] = fmaf(a[i], b[j], acc[i][j]);
        }
        __syncthreads();
    }

    float* outp = &g_part[z * BATCH * DM];
    #pragma unroll
    for (int i = 0; i < 4; i++)
        *(float4*)&outp[(b0 + ty * 4 + i) * DM + m0 + tx * 4] =
            make_float4(acc[i][0], acc[i][1], acc[i][2], acc[i][3]);
}

// ---------------------------------------------------------------------------
// Phase 3: reduce 16 split-K partials + SiLU. 2 threads per float4 output,
// 8 slabs each (MLP 8), single shfl stage. Grid: 256 blocks x 256 threads.
// ---------------------------------------------------------------------------
__global__ void __launch_bounds__(256) phase3_kernel(float* __restrict__ out)
{
    const int t  = threadIdx.x;
    const int zg = t & 1;
    const int o4 = blockIdx.x * 128 + (t >> 1);
    const int i  = o4 * 4;

    float4 v = make_float4(0.f, 0.f, 0.f, 0.f);
    #pragma unroll
    for (int j = 0; j < 8; j++) {
        const float4 p = *(const float4*)&g_part[(zg * 8 + j) * BATCH * DM + i];
        v.x += p.x; v.y += p.y; v.z += p.z; v.w += p.w;
    }
    v.x += __shfl_xor_sync(0xFFFFFFFFu, v.x, 1);
    v.y += __shfl_xor_sync(0xFFFFFFFFu, v.y, 1);
    v.z += __shfl_xor_sync(0xFFFFFFFFu, v.z, 1);
    v.w += __shfl_xor_sync(0xFFFFFFFFu, v.w, 1);
    if (zg == 0) {
        float4 o;
        o.x = v.x / (1.0f + __expf(-v.x));
        o.y = v.y / (1.0f + __expf(-v.y));
        o.z = v.z / (1.0f + __expf(-v.z));
        o.w = v.w / (1.0f + __expf(-v.w));
        *(float4*)&out[i] = o;
    }
}

extern "C" void kernel_launch(void* const* d_in, const int* in_sizes, int n_in,
                              void* d_out, int out_size)
{
    (void)in_sizes; (void)n_in; (void)out_size;
    const float* xr = (const float*)d_in[0];
    const float* xi = (const float*)d_in[1];
    const float* W  = (const float*)d_in[2];
    const float* Bm = (const float*)d_in[3];
    const float* PC = (const float*)d_in[4];
    const float* PS = (const float*)d_in[5];
    float* out = (float*)d_out;

    // Zero the phase-1 RED accumulator (graph-legal memset node).
    void* p_sums = nullptr;
    cudaGetSymbolAddress(&p_sums, g_sums);
    cudaMemsetAsync(p_sums, 0, (size_t)BATCH * KTOT * sizeof(float));

    dim3 g1(NN / NT, BATCH / BT, ZSPLIT);      // 2048 blocks
    phase1_kernel<<<g1, P1_THREADS>>>(xr, xi, W, Bm);

    dim3 g2(DM / BN, BATCH / BM, SPLITK);      // 8 x 4 x 16 = 512 blocks
    phase2_kernel<<<g2, 256>>>(PC, PS);

    phase3_kernel<<<BATCH * DM / 4 / 128, 256>>>(out);   // 256 blocks
}